// round 1
// baseline (speedup 1.0000x reference)
#include <cuda_runtime.h>
#include <math.h>

#define BB 64
#define TT 1024
#define DD 512
#define HH 512

// ---- persistent state (device globals; no allocation allowed) ----
__device__ float g_h[BB * HH];   // h state exchange buffer [64][512]
__device__ int   g_bar[16];      // per-group arrival counters (monotonic per launch)

// ===================== init: reset barrier counters (every launch / replay) ============
__global__ void init_kernel() {
    if (threadIdx.x < 16) g_bar[threadIdx.x] = 0;
}

// ===================== Phase 1: xw = x @ W[0:512] + b, written into out ================
// M=65536, N=512, K=512. BM=128, BN=64, BK=16, 256 threads, 8x4 per thread.
__global__ void __launch_bounds__(256) gemm_xw_kernel(
    const float* __restrict__ x, const float* __restrict__ Wg,
    const float* __restrict__ bias, float* __restrict__ C)
{
    __shared__ float As[16][132];  // [BK][BM+4]  (pad kills scatter-store conflicts)
    __shared__ float Bs[16][68];   // [BK][BN+4]

    const int tid = threadIdx.x;
    const int tn  = tid & 15;      // col group: cols tn*4 .. tn*4+3
    const int tm  = tid >> 4;      // row group: rows tm*8 .. tm*8+7
    const int m0  = blockIdx.x * 128;
    const int n0  = blockIdx.y * 64;

    float acc[8][4];
#pragma unroll
    for (int i = 0; i < 8; i++)
#pragma unroll
        for (int j = 0; j < 4; j++) acc[i][j] = 0.0f;

    for (int k0 = 0; k0 < 512; k0 += 16) {
        // load A tile 128x16 (512 float4, 2 per thread), store transposed
#pragma unroll
        for (int i = tid; i < 512; i += 256) {
            int m = i >> 2, kq = i & 3;
            float4 v = *(const float4*)(x + (size_t)(m0 + m) * 512 + k0 + kq * 4);
            As[kq * 4 + 0][m] = v.x;
            As[kq * 4 + 1][m] = v.y;
            As[kq * 4 + 2][m] = v.z;
            As[kq * 4 + 3][m] = v.w;
        }
        // load B tile 16x64 (256 float4, 1 per thread)
        {
            int kk = tid >> 4, nq = tid & 15;
            float4 v = *(const float4*)(Wg + (size_t)(k0 + kk) * 512 + n0 + nq * 4);
            *(float4*)&Bs[kk][nq * 4] = v;
        }
        __syncthreads();
#pragma unroll
        for (int kk = 0; kk < 16; kk++) {
            float4 bv = *(const float4*)&Bs[kk][tn * 4];
            float a[8];
#pragma unroll
            for (int i = 0; i < 8; i++) a[i] = As[kk][tm * 8 + i];
#pragma unroll
            for (int i = 0; i < 8; i++) {
                acc[i][0] += a[i] * bv.x;
                acc[i][1] += a[i] * bv.y;
                acc[i][2] += a[i] * bv.z;
                acc[i][3] += a[i] * bv.w;
            }
        }
        __syncthreads();
    }

    float b0 = bias[n0 + tn * 4 + 0];
    float b1 = bias[n0 + tn * 4 + 1];
    float b2 = bias[n0 + tn * 4 + 2];
    float b3 = bias[n0 + tn * 4 + 3];
#pragma unroll
    for (int i = 0; i < 8; i++) {
        int m = m0 + tm * 8 + i;
        float4 o;
        o.x = acc[i][0] + b0;
        o.y = acc[i][1] + b1;
        o.z = acc[i][2] + b2;
        o.w = acc[i][3] + b3;
        *(float4*)(C + (size_t)m * 512 + n0 + tn * 4) = o;
    }
}

// ===================== Phase 2: sequential recurrence ==================================
// 16 groups x 8 CTAs. Group g: batches 4g..4g+3. CTA c: output cols 64c..64c+63.
// SMEM: Wh slice [512][66] fp32 + h staging [4][512] + partial-sum buffer [8][260].
#define WPAD 66
#define SMEM_WHS   (512 * WPAD)                 // 33792 floats
#define SMEM_HS    (SMEM_WHS)                   // float4 region starts here (16B aligned)
#define SMEM_RED   (SMEM_WHS + 2048)
#define SMEM_FLOATS (SMEM_WHS + 2048 + 8 * 260) // 37920 floats = 151680 bytes

__global__ void __launch_bounds__(256, 1) recurrent_kernel(
    const float* __restrict__ Wg, float* __restrict__ out)
{
    extern __shared__ float smem[];
    float*  Whs = smem;                         // [512][WPAD]
    float4* hs4 = (float4*)(smem + SMEM_HS);    // [4 batches][128 float4]
    float*  red = smem + SMEM_RED;              // [8 kc][260]

    const int tid = threadIdx.x;
    const int g   = blockIdx.x >> 3;   // group 0..15
    const int c   = blockIdx.x & 7;    // col-slice 0..7

    // ---- load Wh slice: W rows 512..1023, cols 64c..64c+63 ----
    for (int i = tid; i < 512 * 16; i += 256) {
        int k = i >> 4, j4 = i & 15;
        float4 v = ((const float4*)Wg)[(size_t)(512 + k) * 128 + c * 16 + j4];
        float* dst = &Whs[k * WPAD + j4 * 4];
        dst[0] = v.x; dst[1] = v.y; dst[2] = v.z; dst[3] = v.w;
    }
    // ---- zero h state in SMEM (h_{-1} = 0) ----
    hs4[tid]       = make_float4(0.f, 0.f, 0.f, 0.f);
    hs4[tid + 256] = make_float4(0.f, 0.f, 0.f, 0.f);
    __syncthreads();

    const int kc  = tid >> 5;   // K-chunk 0..7 (k in [64*kc, 64*kc+64))
    const int jg  = tid & 31;   // cols 2*jg, 2*jg+1
    const int bo  = tid >> 6;   // epilogue: batch 0..3
    const int col = tid & 63;   // epilogue: column within slice

    float* outrow = out + (size_t)(g * 4 + bo) * TT * HH + c * 64 + col;
    float* hptr   = g_h + (size_t)(g * 4 + bo) * 512 + c * 64 + col;
    volatile int* barp = (volatile int*)&g_bar[g];

    for (int t = 0; t < TT; t++) {
        // prefetch xw (phase-1 result lives in out[b][t][col])
        float xwv = outrow[(size_t)t * HH];

        float acc00 = 0.f, acc01 = 0.f, acc10 = 0.f, acc11 = 0.f;
        float acc20 = 0.f, acc21 = 0.f, acc30 = 0.f, acc31 = 0.f;
#pragma unroll
        for (int kk = 0; kk < 64; kk += 4) {
            int k = kc * 64 + kk;
            int kq = k >> 2;
            float4 h0 = hs4[kq];
            float4 h1 = hs4[128 + kq];
            float4 h2 = hs4[256 + kq];
            float4 h3 = hs4[384 + kq];
            float2 w0 = *(const float2*)&Whs[(k + 0) * WPAD + jg * 2];
            float2 w1 = *(const float2*)&Whs[(k + 1) * WPAD + jg * 2];
            float2 w2 = *(const float2*)&Whs[(k + 2) * WPAD + jg * 2];
            float2 w3 = *(const float2*)&Whs[(k + 3) * WPAD + jg * 2];
            acc00 += h0.x * w0.x; acc00 += h0.y * w1.x; acc00 += h0.z * w2.x; acc00 += h0.w * w3.x;
            acc01 += h0.x * w0.y; acc01 += h0.y * w1.y; acc01 += h0.z * w2.y; acc01 += h0.w * w3.y;
            acc10 += h1.x * w0.x; acc10 += h1.y * w1.x; acc10 += h1.z * w2.x; acc10 += h1.w * w3.x;
            acc11 += h1.x * w0.y; acc11 += h1.y * w1.y; acc11 += h1.z * w2.y; acc11 += h1.w * w3.y;
            acc20 += h2.x * w0.x; acc20 += h2.y * w1.x; acc20 += h2.z * w2.x; acc20 += h2.w * w3.x;
            acc21 += h2.x * w0.y; acc21 += h2.y * w1.y; acc21 += h2.z * w2.y; acc21 += h2.w * w3.y;
            acc30 += h3.x * w0.x; acc30 += h3.y * w1.x; acc30 += h3.z * w2.x; acc30 += h3.w * w3.x;
            acc31 += h3.x * w0.y; acc31 += h3.y * w1.y; acc31 += h3.z * w2.y; acc31 += h3.w * w3.y;
        }
        // stash partial sums (per K-chunk)
        *(float2*)&red[kc * 260 +   0 + jg * 2] = make_float2(acc00, acc01);
        *(float2*)&red[kc * 260 +  64 + jg * 2] = make_float2(acc10, acc11);
        *(float2*)&red[kc * 260 + 128 + jg * 2] = make_float2(acc20, acc21);
        *(float2*)&red[kc * 260 + 192 + jg * 2] = make_float2(acc30, acc31);
        __syncthreads();

        // epilogue: one (batch,col) output per thread
        float z = xwv;
#pragma unroll
        for (int k2 = 0; k2 < 8; k2++) z += red[k2 * 260 + bo * 64 + col];
        float hv = tanhf(z);
        outrow[(size_t)t * HH] = hv;   // overwrite xw with h (this IS the output)
        *hptr = hv;                    // publish for group peers
        __threadfence();
        __syncthreads();               // all stores done + red safe to reuse

        if (t + 1 < TT) {
            if (tid == 0) {
                atomicAdd((int*)&g_bar[g], 1);
                int target = 8 * (t + 1);
                while (*barp < target) { }
                __threadfence();
            }
            __syncthreads();
            // coherent reload of the group's full h (L1 is not coherent across SMs)
            const float4* hb = ((const float4*)g_h) + (size_t)g * 512;
            hs4[tid]       = __ldcg(hb + tid);
            hs4[tid + 256] = __ldcg(hb + tid + 256);
            __syncthreads();
        }
    }
}

// ======================================================================================
extern "C" void kernel_launch(void* const* d_in, const int* in_sizes, int n_in,
                              void* d_out, int out_size) {
    (void)in_sizes; (void)n_in; (void)out_size;
    const float* x  = (const float*)d_in[0];   // [64,1024,512]
    const float* Wg = (const float*)d_in[1];   // [1024,512]
    const float* bb = (const float*)d_in[2];   // [512]
    float* out = (float*)d_out;                // [64,1024,512]

    static int smem_set = 0;
    if (!smem_set) {
        cudaFuncSetAttribute(recurrent_kernel,
                             cudaFuncAttributeMaxDynamicSharedMemorySize,
                             SMEM_FLOATS * (int)sizeof(float));
        smem_set = 1;
    }

    init_kernel<<<1, 32>>>();
    gemm_xw_kernel<<<dim3(512, 8), 256>>>(x, Wg, bb, out);
    recurrent_kernel<<<128, 256, SMEM_FLOATS * sizeof(float)>>>(Wg, out);
}

// round 2
// speedup vs baseline: 1.0153x; 1.0153x over previous
#include <cuda_runtime.h>
#include <math.h>

#define TT 1024
#define HH 512

// ---- persistent state (device globals; no allocation allowed) ----
__device__ float g_h[2][64 * 512];   // double-buffered h exchange [parity][64][512]
__device__ int   g_bar[16];          // per-group arrival counters

// ---- packed f32x2 helpers (sm_103a FFMA2 path, PTX-only) ----
__device__ __forceinline__ unsigned long long pack2(float x, float y) {
    unsigned long long r;
    asm("mov.b64 %0, {%1, %2};" : "=l"(r) : "f"(x), "f"(y));
    return r;
}
__device__ __forceinline__ unsigned long long fma2(unsigned long long a,
                                                   unsigned long long b,
                                                   unsigned long long c) {
    unsigned long long d;
    asm("fma.rn.f32x2 %0, %1, %2, %3;" : "=l"(d) : "l"(a), "l"(b), "l"(c));
    return d;
}
__device__ __forceinline__ unsigned long long add2(unsigned long long a,
                                                   unsigned long long b) {
    unsigned long long d;
    asm("add.rn.f32x2 %0, %1, %2;" : "=l"(d) : "l"(a), "l"(b));
    return d;
}
__device__ __forceinline__ float2 unpack2(unsigned long long v) {
    float2 r;
    asm("mov.b64 {%0, %1}, %2;" : "=f"(r.x), "=f"(r.y) : "l"(v));
    return r;
}

// ===================== Phase 1: xw = x @ W[0:512] + b, written into out ================
// M=65536, N=512, K=512. BM=128, BN=64, BK=16, 256 threads, 8x4 per thread (f32x2 pairs).
__global__ void __launch_bounds__(256) gemm_xw_kernel(
    const float* __restrict__ x, const float* __restrict__ Wg,
    const float* __restrict__ bias, float* __restrict__ C)
{
    // block (0,0) resets the phase-2 barrier counters (phase 2 launches after us)
    if (blockIdx.x == 0 && blockIdx.y == 0 && threadIdx.x < 16)
        g_bar[threadIdx.x] = 0;

    __shared__ float As[16][132];  // [BK][BM+4]
    __shared__ float Bs[16][68];   // [BK][BN+4]

    const int tid = threadIdx.x;
    const int tn  = tid & 15;      // col group: cols tn*4 .. tn*4+3
    const int tm  = tid >> 4;      // row group: rows tm*8 .. tm*8+7
    const int m0  = blockIdx.x * 128;
    const int n0  = blockIdx.y * 64;

    unsigned long long acc[8][2];
#pragma unroll
    for (int i = 0; i < 8; i++) { acc[i][0] = 0ull; acc[i][1] = 0ull; }

    for (int k0 = 0; k0 < 512; k0 += 16) {
#pragma unroll
        for (int i = tid; i < 512; i += 256) {
            int m = i >> 2, kq = i & 3;
            float4 v = *(const float4*)(x + (size_t)(m0 + m) * 512 + k0 + kq * 4);
            As[kq * 4 + 0][m] = v.x;
            As[kq * 4 + 1][m] = v.y;
            As[kq * 4 + 2][m] = v.z;
            As[kq * 4 + 3][m] = v.w;
        }
        {
            int kk = tid >> 4, nq = tid & 15;
            float4 v = *(const float4*)(Wg + (size_t)(k0 + kk) * 512 + n0 + nq * 4);
            *(float4*)&Bs[kk][nq * 4] = v;
        }
        __syncthreads();
#pragma unroll
        for (int kk = 0; kk < 16; kk++) {
            ulonglong2 bb = *(const ulonglong2*)&Bs[kk][tn * 4];  // 16B aligned
#pragma unroll
            for (int i = 0; i < 8; i++) {
                float a = As[kk][tm * 8 + i];
                unsigned long long ap = pack2(a, a);
                acc[i][0] = fma2(ap, bb.x, acc[i][0]);
                acc[i][1] = fma2(ap, bb.y, acc[i][1]);
            }
        }
        __syncthreads();
    }

    float b0 = bias[n0 + tn * 4 + 0];
    float b1 = bias[n0 + tn * 4 + 1];
    float b2 = bias[n0 + tn * 4 + 2];
    float b3 = bias[n0 + tn * 4 + 3];
#pragma unroll
    for (int i = 0; i < 8; i++) {
        int m = m0 + tm * 8 + i;
        float2 p0 = unpack2(acc[i][0]);
        float2 p1 = unpack2(acc[i][1]);
        float4 o;
        o.x = p0.x + b0;
        o.y = p0.y + b1;
        o.z = p1.x + b2;
        o.w = p1.y + b3;
        *(float4*)(C + (size_t)m * 512 + n0 + tn * 4) = o;
    }
}

// ===================== Phase 2: sequential recurrence ==================================
// 16 groups x 8 CTAs (128 persistent). Group g: batches 4g..4g+3. CTA c: cols 64c..64c+63.
// Wh slice lives entirely in REGISTERS (64 x u64 per thread = 128KB/CTA).
// h state lives in SMEM as duplicated (h,h) pairs -> broadcast LDS.128 feeds fma2 directly.
__global__ void __launch_bounds__(256, 1) recurrent_kernel(
    const float* __restrict__ Wg, float* __restrict__ out)
{
    __shared__ float4 hsdup[4 * 256];   // [batch][k/2] : {h_k,h_k,h_{k+1},h_{k+1}}
    __shared__ float  red[8 * 260];     // per-K-chunk partial sums

    const int tid = threadIdx.x;
    const int g   = blockIdx.x >> 3;    // group 0..15
    const int c   = blockIdx.x & 7;     // col-slice 0..7
    const int kc  = tid >> 5;           // K-chunk 0..7 (k in [64kc, 64kc+64))
    const int jg  = tid & 31;           // cols 2jg, 2jg+1 within slice
    const int bo  = tid >> 6;           // epilogue batch 0..3
    const int col = tid & 63;           // epilogue column within slice

    // ---- Wh slice into registers: w[k] = (Wh[kc*64+k][c*64+2jg], [..+2jg+1]) ----
    unsigned long long w[64];
#pragma unroll
    for (int k = 0; k < 64; k++) {
        const float* p = Wg + (size_t)(512 + kc * 64 + k) * 512 + c * 64 + jg * 2;
        w[k] = *(const unsigned long long*)p;  // 8B aligned, coalesced
    }
    // ---- h_{-1} = 0 ----
    for (int i = tid; i < 1024; i += 256)
        hsdup[i] = make_float4(0.f, 0.f, 0.f, 0.f);
    __syncthreads();

    float* outrow = out + (size_t)(g * 4 + bo) * TT * HH + c * 64 + col;
    const int hoff = (g * 4 + bo) * 512 + c * 64 + col;
    int* barp = &g_bar[g];

    for (int t = 0; t < TT; t++) {
        float xwv = outrow[(size_t)t * HH];   // phase-1 result, issued early

        // 8 accumulator chains (4 batches x even/odd-k) for ILP
        unsigned long long ae0 = 0, ae1 = 0, ae2 = 0, ae3 = 0;
        unsigned long long ao0 = 0, ao1 = 0, ao2 = 0, ao3 = 0;
        const float4* h0 = &hsdup[0 * 256 + kc * 32];
        const float4* h1 = &hsdup[1 * 256 + kc * 32];
        const float4* h2 = &hsdup[2 * 256 + kc * 32];
        const float4* h3 = &hsdup[3 * 256 + kc * 32];
#pragma unroll
        for (int k2 = 0; k2 < 32; k2++) {     // k2 = k/2 within chunk
            float4 ha = h0[k2];
            float4 hb = h1[k2];
            float4 hc = h2[k2];
            float4 hd = h3[k2];
            unsigned long long we = w[2 * k2], wo = w[2 * k2 + 1];
            ae0 = fma2(pack2(ha.x, ha.y), we, ae0);
            ao0 = fma2(pack2(ha.z, ha.w), wo, ao0);
            ae1 = fma2(pack2(hb.x, hb.y), we, ae1);
            ao1 = fma2(pack2(hb.z, hb.w), wo, ao1);
            ae2 = fma2(pack2(hc.x, hc.y), we, ae2);
            ao2 = fma2(pack2(hc.z, hc.w), wo, ao2);
            ae3 = fma2(pack2(hd.x, hd.y), we, ae3);
            ao3 = fma2(pack2(hd.z, hd.w), wo, ao3);
        }
        unsigned long long a0 = add2(ae0, ao0);
        unsigned long long a1 = add2(ae1, ao1);
        unsigned long long a2 = add2(ae2, ao2);
        unsigned long long a3 = add2(ae3, ao3);

        // stash per-chunk partials
        *(float2*)&red[kc * 260 +   0 + jg * 2] = unpack2(a0);
        *(float2*)&red[kc * 260 +  64 + jg * 2] = unpack2(a1);
        *(float2*)&red[kc * 260 + 128 + jg * 2] = unpack2(a2);
        *(float2*)&red[kc * 260 + 192 + jg * 2] = unpack2(a3);
        __syncthreads();

        // epilogue: one (batch, col) output per thread
        float z = xwv;
#pragma unroll
        for (int k2 = 0; k2 < 8; k2++) z += red[k2 * 260 + bo * 64 + col];
        float hv = tanhf(z);
        outrow[(size_t)t * HH] = hv;               // this IS the output
        __stcg(&g_h[t & 1][hoff], hv);             // publish (write-through L2)
        __syncthreads();                           // all stores issued; red reusable

        if (t + 1 < TT) {
            if (tid == 0) {
                // release-arrive: cumulativity (via bar.sync above) covers all threads' stores
                asm volatile("red.release.gpu.global.add.s32 [%0], 1;"
                             :: "l"(barp) : "memory");
                int target = 8 * (t + 1), v;
                do {
                    asm volatile("ld.acquire.gpu.global.s32 %0, [%1];"
                                 : "=r"(v) : "l"(barp) : "memory");
                } while (v < target);
            }
            __syncthreads();
            // coherent reload of group h -> duplicated smem format
            const float4* src = (const float4*)&g_h[t & 1][g * 2048];
#pragma unroll
            for (int r = 0; r < 2; r++) {
                int fi = tid + r * 256;            // float4 index, 512 total
                float4 v = __ldcg(src + fi);
                int b  = fi >> 7;                  // batch
                int q  = (fi * 2) & 255;           // k/2 within batch
                hsdup[b * 256 + q + 0] = make_float4(v.x, v.x, v.y, v.y);
                hsdup[b * 256 + q + 1] = make_float4(v.z, v.z, v.w, v.w);
            }
            __syncthreads();
        }
    }
}

// ======================================================================================
extern "C" void kernel_launch(void* const* d_in, const int* in_sizes, int n_in,
                              void* d_out, int out_size) {
    (void)in_sizes; (void)n_in; (void)out_size;
    const float* x  = (const float*)d_in[0];   // [64,1024,512]
    const float* Wg = (const float*)d_in[1];   // [1024,512]
    const float* bb = (const float*)d_in[2];   // [512]
    float* out = (float*)d_out;                // [64,1024,512]

    gemm_xw_kernel<<<dim3(512, 8), 256>>>(x, Wg, bb, out);
    recurrent_kernel<<<128, 256>>>(Wg, out);
}